// round 3
// baseline (speedup 1.0000x reference)
#include <cuda_runtime.h>
#include <cuda_fp16.h>
#include <cstdint>

// Y[8192,11008] = X[8192,4096] (fp16-valued fp32) @ dequant(W4[11008,4096]).T
#define M_DIM 8192
#define N_DIM 11008
#define K_DIM 4096
#define BM 128
#define BN 128
#define BK 64
#define NTHREADS 256
// shared: 2 buffers x (A 128x64 + B 128x64) fp16 = 65536 bytes
#define SMEM_BYTES 65536

__device__ __forceinline__ void ldsm_x4(uint32_t* r, uint32_t addr) {
    asm volatile("ldmatrix.sync.aligned.m8n8.x4.shared.b16 {%0,%1,%2,%3}, [%4];\n"
        : "=r"(r[0]), "=r"(r[1]), "=r"(r[2]), "=r"(r[3]) : "r"(addr));
}

__device__ __forceinline__ void mma_16816(float* c, const uint32_t* a, uint32_t b0, uint32_t b1) {
    asm volatile("mma.sync.aligned.m16n8k16.row.col.f32.f16.f16.f32 "
        "{%0,%1,%2,%3}, {%4,%5,%6,%7}, {%8,%9}, {%0,%1,%2,%3};\n"
        : "+f"(c[0]), "+f"(c[1]), "+f"(c[2]), "+f"(c[3])
        : "r"(a[0]), "r"(a[1]), "r"(a[2]), "r"(a[3]), "r"(b0), "r"(b1));
}

__global__ void __launch_bounds__(NTHREADS, 1)
int4_gemm_kernel(const float* __restrict__ x,
                 const int*   __restrict__ wp,
                 const float* __restrict__ scales,
                 float*       __restrict__ out)
{
    extern __shared__ __half sm[];
    __half* As = sm;                       // 2 x 8192 halves
    __half* Bs = sm + 2 * BM * BK;         // 2 x 8192 halves

    const uint32_t smem_u = (uint32_t)__cvta_generic_to_shared(sm);
    const uint32_t As_u = smem_u;
    const uint32_t Bs_u = smem_u + 2 * BM * BK * 2;

    const int tid  = threadIdx.x;
    const int warp = tid >> 5;
    const int lane = tid & 31;
    const int m0 = blockIdx.y * BM;
    const int n0 = blockIdx.x * BN;

    // ---- gmem -> smem staging map: 128 rows x 8 chunks (8 halves); 4 chunks/thread ----
    const int cv    = tid & 7;        // chunk (8 cols) within row
    const int rbase = tid >> 3;       // row 0..31 (+32*i)
    const int cvs   = cv ^ (rbase & 7);  // XOR swizzle (row%8 invariant under +32)

    const float* xg = x  + (size_t)(m0 + rbase) * K_DIM + cv * 8;
    const int*   wg = wp + (size_t)(n0 + rbase) * (K_DIM / 2) + cv * 4;
    const float* sg = scales + (size_t)(n0 + rbase) * (K_DIM / 128);

    const int st_half = rbase * BK + cvs * 8;   // element offset within a buffer

    // ---- warp tiling: 8 warps = 2(m) x 4(n); warp tile 64x32 ----
    const int wm  = (warp >> 2) * 64;
    const int wn  = (warp & 3) * 32;
    const int lrA = lane & 15;
    const int lkA = lane >> 4;
    const int lrB = (lane & 7) + ((lane >> 4) << 3);
    const int lkB = (lane >> 3) & 1;

    float acc[4][4][4];
    #pragma unroll
    for (int i = 0; i < 4; i++)
        #pragma unroll
        for (int j = 0; j < 4; j++)
            #pragma unroll
            for (int q = 0; q < 4; q++) acc[i][j][q] = 0.f;

    const int KT = K_DIM / BK;  // 64 k-tiles

    // ================= prologue: stage tile 0 into buffer 0 =================
    #pragma unroll
    for (int i = 0; i < 4; i++) {
        float4 a0 = *(const float4*)(xg + (size_t)(32 * i) * K_DIM);
        float4 a1 = *(const float4*)(xg + (size_t)(32 * i) * K_DIM + 4);
        union { uint4 u; __half2 h[4]; } pa;
        pa.h[0] = __floats2half2_rn(a0.x, a0.y);
        pa.h[1] = __floats2half2_rn(a0.z, a0.w);
        pa.h[2] = __floats2half2_rn(a1.x, a1.y);
        pa.h[3] = __floats2half2_rn(a1.z, a1.w);
        *(uint4*)(As + st_half + i * 2048) = pa.u;

        uint4 wv = *(const uint4*)(wg + (size_t)(32 * i) * (K_DIM / 2));
        float s  = sg[(size_t)(32 * i) * (K_DIM / 128)];
        uint32_t ws[4] = {wv.x, wv.y, wv.z, wv.w};
        union { uint4 u; __half2 h[4]; } pb;
        #pragma unroll
        for (int q = 0; q < 4; q++) {
            int w = (int)ws[q];
            pb.h[q] = __floats2half2_rn(s * (float)((w & 15) - 8),
                                        s * (float)(((w >> 4) & 15) - 8));
        }
        *(uint4*)(Bs + st_half + i * 2048) = pb.u;
    }
    __syncthreads();

    // ================= main loop =================
    for (int kt = 0; kt < KT; kt++) {
        const int  buf  = kt & 1;
        const int  nbuf = buf ^ 1;
        const bool more = (kt + 1) < KT;

        float4 av[4][2];
        uint4  wv[4];
        float  s4[4];
        if (more) {
            const int g = (kt + 1) >> 1;  // scale group (128 k per group)
            #pragma unroll
            for (int i = 0; i < 4; i++) {
                const float* xr = xg + (size_t)(32 * i) * K_DIM + (kt + 1) * BK;
                av[i][0] = *(const float4*)(xr);
                av[i][1] = *(const float4*)(xr + 4);
                wv[i] = *(const uint4*)(wg + (size_t)(32 * i) * (K_DIM / 2) + (kt + 1) * (BK / 2));
                s4[i] = sg[(size_t)(32 * i) * (K_DIM / 128) + g];
            }
        }

        // ---- compute on current buffer ----
        const uint32_t ab = As_u + buf * 16384;
        const uint32_t bb = Bs_u + buf * 16384;
        #pragma unroll
        for (int ks = 0; ks < 4; ks++) {
            uint32_t a[4][4], b[2][4];
            #pragma unroll
            for (int i = 0; i < 4; i++) {
                int r  = wm + i * 16 + lrA;
                int ch = 2 * ks + lkA;
                ldsm_x4(a[i], ab + (uint32_t)(r * BK + ((ch ^ (r & 7)) << 3)) * 2);
            }
            #pragma unroll
            for (int p = 0; p < 2; p++) {
                int r  = wn + p * 16 + lrB;
                int ch = 2 * ks + lkB;
                ldsm_x4(b[p], bb + (uint32_t)(r * BK + ((ch ^ (r & 7)) << 3)) * 2);
            }
            #pragma unroll
            for (int i = 0; i < 4; i++)
                #pragma unroll
                for (int j = 0; j < 4; j++)
                    mma_16816(acc[i][j], a[i], b[j >> 1][(j & 1) * 2], b[j >> 1][(j & 1) * 2 + 1]);
        }

        if (more) {
            // stage next tile (convert in regs -> smem nbuf)
            #pragma unroll
            for (int i = 0; i < 4; i++) {
                union { uint4 u; __half2 h[4]; } pa;
                pa.h[0] = __floats2half2_rn(av[i][0].x, av[i][0].y);
                pa.h[1] = __floats2half2_rn(av[i][0].z, av[i][0].w);
                pa.h[2] = __floats2half2_rn(av[i][1].x, av[i][1].y);
                pa.h[3] = __floats2half2_rn(av[i][1].z, av[i][1].w);
                *(uint4*)(As + nbuf * (BM * BK) + st_half + i * 2048) = pa.u;

                uint32_t ws[4] = {wv[i].x, wv[i].y, wv[i].z, wv[i].w};
                union { uint4 u; __half2 h[4]; } pb;
                #pragma unroll
                for (int q = 0; q < 4; q++) {
                    int w = (int)ws[q];
                    pb.h[q] = __floats2half2_rn(s4[i] * (float)((w & 15) - 8),
                                                s4[i] * (float)(((w >> 4) & 15) - 8));
                }
                *(uint4*)(Bs + nbuf * (BM * BK) + st_half + i * 2048) = pb.u;
            }
            __syncthreads();
        }
    }

    // ================= epilogue (fp32 out, rounded through fp16 like the ref) =================
    const int g  = lane >> 2;
    const int tc = lane & 3;
    #pragma unroll
    for (int i = 0; i < 4; i++) {
        #pragma unroll
        for (int j = 0; j < 4; j++) {
            int row = m0 + wm + i * 16 + g;
            int col = n0 + wn + j * 8 + tc * 2;
            float2 v0, v1;
            v0.x = __half2float(__float2half_rn(acc[i][j][0]));
            v0.y = __half2float(__float2half_rn(acc[i][j][1]));
            v1.x = __half2float(__float2half_rn(acc[i][j][2]));
            v1.y = __half2float(__float2half_rn(acc[i][j][3]));
            *(float2*)(out + (size_t)row * N_DIM + col)       = v0;
            *(float2*)(out + (size_t)(row + 8) * N_DIM + col) = v1;
        }
    }
}

extern "C" void kernel_launch(void* const* d_in, const int* in_sizes, int n_in,
                              void* d_out, int out_size)
{
    // Identify inputs by element count (dtype-independent):
    // x: 4*2048*4096 = 33554432, weight_packed: 11008*2048 = 22544384,
    // scales: 11008*32 = 352256
    const float* x      = (const float*)d_in[0];
    const int*   wp     = (const int*)d_in[1];
    const float* scales = (const float*)d_in[2];
    for (int i = 0; i < n_in; i++) {
        if (in_sizes[i] == 33554432)      x      = (const float*)d_in[i];
        else if (in_sizes[i] == 22544384) wp     = (const int*)d_in[i];
        else if (in_sizes[i] == 352256)   scales = (const float*)d_in[i];
    }
    float* out = (float*)d_out;

    cudaFuncSetAttribute(int4_gemm_kernel,
                         cudaFuncAttributeMaxDynamicSharedMemorySize, SMEM_BYTES);

    dim3 grid(N_DIM / BN, M_DIM / BM);  // (86, 64)
    int4_gemm_kernel<<<grid, NTHREADS, SMEM_BYTES>>>(x, wp, scales, out);
}

// round 4
// speedup vs baseline: 1.2200x; 1.2200x over previous
#include <cuda_runtime.h>
#include <cuda_fp16.h>
#include <cstdint>

// Y[8192,11008] = X[8192,4096] (fp16-valued fp32) @ dequant(W4[11008,4096]).T
#define M_DIM 8192
#define N_DIM 11008
#define K_DIM 4096
#define BM 128
#define BN 128
#define BK 64
#define NTHREADS 256
#define STAGES 3
// shared: 3 A stages (16KB) + 2 B buffers (16KB) = 80KB
#define SMEM_BYTES (STAGES * BM * BK * 2 + 2 * BN * BK * 2)

// one-time fp16 copy of X (64 MB device scratch)
__device__ __align__(16) __half g_xh[(size_t)M_DIM * K_DIM];

__device__ __forceinline__ void cp_async16(uint32_t dst, const void* src) {
    asm volatile("cp.async.cg.shared.global [%0], [%1], 16;\n" :: "r"(dst), "l"(src));
}
__device__ __forceinline__ void cp_commit() { asm volatile("cp.async.commit_group;\n"); }
__device__ __forceinline__ void cp_wait0()  { asm volatile("cp.async.wait_group 0;\n"); }
__device__ __forceinline__ void cp_wait1()  { asm volatile("cp.async.wait_group 1;\n"); }

__device__ __forceinline__ void ldsm_x4(uint32_t* r, uint32_t addr) {
    asm volatile("ldmatrix.sync.aligned.m8n8.x4.shared.b16 {%0,%1,%2,%3}, [%4];\n"
        : "=r"(r[0]), "=r"(r[1]), "=r"(r[2]), "=r"(r[3]) : "r"(addr));
}

__device__ __forceinline__ void mma_16816(float* c, const uint32_t* a, uint32_t b0, uint32_t b1) {
    asm volatile("mma.sync.aligned.m16n8k16.row.col.f32.f16.f16.f32 "
        "{%0,%1,%2,%3}, {%4,%5,%6,%7}, {%8,%9}, {%0,%1,%2,%3};\n"
        : "+f"(c[0]), "+f"(c[1]), "+f"(c[2]), "+f"(c[3])
        : "r"(a[0]), "r"(a[1]), "r"(a[2]), "r"(a[3]), "r"(b0), "r"(b1));
}

// ---------------- kernel 1: X fp32 -> fp16 scratch ----------------
__global__ void __launch_bounds__(256, 4)
convert_x_kernel(const float* __restrict__ x)
{
    size_t i = ((size_t)blockIdx.x * 256 + threadIdx.x) * 8;
    float4 a0 = *(const float4*)(x + i);
    float4 a1 = *(const float4*)(x + i + 4);
    union { uint4 u; __half2 h[4]; } p;
    p.h[0] = __floats2half2_rn(a0.x, a0.y);
    p.h[1] = __floats2half2_rn(a0.z, a0.w);
    p.h[2] = __floats2half2_rn(a1.x, a1.y);
    p.h[3] = __floats2half2_rn(a1.z, a1.w);
    *(uint4*)(g_xh + i) = p.u;
}

// ---------------- kernel 2: fused dequant GEMM ----------------
__global__ void __launch_bounds__(NTHREADS, 1)
int4_gemm_kernel(const int*   __restrict__ wp,
                 const float* __restrict__ scales,
                 float*       __restrict__ out)
{
    extern __shared__ __half sm[];
    __half* Bs = sm + STAGES * BM * BK;          // after 3 A stages

    const uint32_t smem_u = (uint32_t)__cvta_generic_to_shared(sm);
    const uint32_t As_u = smem_u;                         // 3 x 16384 B
    const uint32_t Bs_u = smem_u + STAGES * BM * BK * 2;  // 2 x 16384 B

    const int tid  = threadIdx.x;
    const int warp = tid >> 5;
    const int lane = tid & 31;
    const int m0 = blockIdx.y * BM;
    const int n0 = blockIdx.x * BN;

    // ---- staging map: 128 rows x 8 chunks (8 halves); 4 chunks/thread ----
    const int cv    = tid & 7;
    const int rbase = tid >> 3;          // 0..31 (+32*i)
    const int cvs   = cv ^ (rbase & 7);  // XOR swizzle (row%8 invariant under +32)

    const __half* xg = g_xh + (size_t)(m0 + rbase) * K_DIM + cv * 8;
    const int*    wg = wp   + (size_t)(n0 + rbase) * (K_DIM / 2) + cv * 4;
    const float*  sg = scales + (size_t)(n0 + rbase) * (K_DIM / 128);

    const uint32_t st_off = ((uint32_t)(rbase * BK + cvs * 8)) * 2;  // bytes, +i*4096

    // ---- warp tiling: 8 warps = 2(m) x 4(n); warp tile 64x32 ----
    const int wm  = (warp >> 2) * 64;
    const int wn  = (warp & 3) * 32;
    const int lrA = lane & 15;
    const int lkA = lane >> 4;
    const int lrB = (lane & 7) + ((lane >> 4) << 3);
    const int lkB = (lane >> 3) & 1;

    float acc[4][4][4];
    #pragma unroll
    for (int i = 0; i < 4; i++)
        #pragma unroll
        for (int j = 0; j < 4; j++)
            #pragma unroll
            for (int q = 0; q < 4; q++) acc[i][j][q] = 0.f;

    const int KT = K_DIM / BK;  // 64

    // ================= prologue =================
    // A stages 0 and 1 in flight
    #pragma unroll
    for (int s = 0; s < 2; s++) {
        #pragma unroll
        for (int i = 0; i < 4; i++)
            cp_async16(As_u + s * 16384 + st_off + i * 4096,
                       xg + (size_t)(32 * i) * K_DIM + s * BK);
        cp_commit();
    }
    // B tile 0 -> buf 0
    #pragma unroll
    for (int i = 0; i < 4; i++) {
        uint4 wv = *(const uint4*)(wg + (size_t)(32 * i) * (K_DIM / 2));
        float s  = sg[(size_t)(32 * i) * (K_DIM / 128)];
        uint32_t ws[4] = {wv.x, wv.y, wv.z, wv.w};
        union { uint4 u; __half2 h[4]; } pb;
        #pragma unroll
        for (int q = 0; q < 4; q++) {
            int w = (int)ws[q];
            pb.h[q] = __floats2half2_rn(s * (float)((w & 15) - 8),
                                        s * (float)(((w >> 4) & 15) - 8));
        }
        *(uint4*)(Bs + st_off / 2 + i * 2048) = pb.u;
    }
    cp_wait1();          // A stage 0 complete
    __syncthreads();

    // ================= main loop =================
    for (int kt = 0; kt < KT; kt++) {
        const int abuf = kt % STAGES;
        const int bbuf = kt & 1;

        // issue A(kt+2)
        if (kt + 2 < KT) {
            const int s = (kt + 2) % STAGES;
            #pragma unroll
            for (int i = 0; i < 4; i++)
                cp_async16(As_u + s * 16384 + st_off + i * 4096,
                           xg + (size_t)(32 * i) * K_DIM + (kt + 2) * BK);
            cp_commit();
        }

        // prefetch B(kt+1) packed + scales into regs
        uint4 wv[4];
        float s4[4];
        if (kt + 1 < KT) {
            const int g = (kt + 1) >> 1;
            #pragma unroll
            for (int i = 0; i < 4; i++) {
                wv[i] = *(const uint4*)(wg + (size_t)(32 * i) * (K_DIM / 2) + (kt + 1) * (BK / 2));
                s4[i] = sg[(size_t)(32 * i) * (K_DIM / 128) + g];
            }
        }

        // ---- compute ktile kt ----
        const uint32_t ab = As_u + abuf * 16384;
        const uint32_t bb = Bs_u + bbuf * 16384;
        #pragma unroll
        for (int ks = 0; ks < 4; ks++) {
            uint32_t a[4][4], b[2][4];
            #pragma unroll
            for (int i = 0; i < 4; i++) {
                int r  = wm + i * 16 + lrA;
                int ch = 2 * ks + lkA;
                ldsm_x4(a[i], ab + (uint32_t)(r * BK + ((ch ^ (r & 7)) << 3)) * 2);
            }
            #pragma unroll
            for (int p = 0; p < 2; p++) {
                int r  = wn + p * 16 + lrB;
                int ch = 2 * ks + lkB;
                ldsm_x4(b[p], bb + (uint32_t)(r * BK + ((ch ^ (r & 7)) << 3)) * 2);
            }
            #pragma unroll
            for (int i = 0; i < 4; i++)
                #pragma unroll
                for (int j = 0; j < 4; j++)
                    mma_16816(acc[i][j], a[i], b[j >> 1][(j & 1) * 2], b[j >> 1][(j & 1) * 2 + 1]);
        }

        // dequant B(kt+1) -> other buffer, then close stage
        if (kt + 1 < KT) {
            #pragma unroll
            for (int i = 0; i < 4; i++) {
                uint32_t ws[4] = {wv[i].x, wv[i].y, wv[i].z, wv[i].w};
                union { uint4 u; __half2 h[4]; } pb;
                #pragma unroll
                for (int q = 0; q < 4; q++) {
                    int w = (int)ws[q];
                    pb.h[q] = __floats2half2_rn(s4[i] * (float)((w & 15) - 8),
                                                s4[i] * (float)(((w >> 4) & 15) - 8));
                }
                *(uint4*)(Bs + (bbuf ^ 1) * (BN * BK) + st_off / 2 + i * 2048) = pb.u;
            }
            // A(kt+1) must be complete before next iter reads it
            if (kt + 2 < KT) cp_wait1(); else cp_wait0();
            __syncthreads();
        }
    }

    // ================= epilogue (fp32 out, rounded through fp16 like ref) =================
    const int g  = lane >> 2;
    const int tc = lane & 3;
    #pragma unroll
    for (int i = 0; i < 4; i++) {
        #pragma unroll
        for (int j = 0; j < 4; j++) {
            int row = m0 + wm + i * 16 + g;
            int col = n0 + wn + j * 8 + tc * 2;
            float2 v0, v1;
            v0.x = __half2float(__float2half_rn(acc[i][j][0]));
            v0.y = __half2float(__float2half_rn(acc[i][j][1]));
            v1.x = __half2float(__float2half_rn(acc[i][j][2]));
            v1.y = __half2float(__float2half_rn(acc[i][j][3]));
            *(float2*)(out + (size_t)row * N_DIM + col)       = v0;
            *(float2*)(out + (size_t)(row + 8) * N_DIM + col) = v1;
        }
    }
}

extern "C" void kernel_launch(void* const* d_in, const int* in_sizes, int n_in,
                              void* d_out, int out_size)
{
    // identify inputs by element count
    const float* x      = (const float*)d_in[0];
    const int*   wp     = (const int*)d_in[1];
    const float* scales = (const float*)d_in[2];
    for (int i = 0; i < n_in; i++) {
        if (in_sizes[i] == 33554432)      x      = (const float*)d_in[i];
        else if (in_sizes[i] == 22544384) wp     = (const int*)d_in[i];
        else if (in_sizes[i] == 352256)   scales = (const float*)d_in[i];
    }
    float* out = (float*)d_out;

    // pass 1: X -> fp16 scratch
    convert_x_kernel<<<(size_t)M_DIM * K_DIM / (256 * 8), 256>>>(x);

    // pass 2: GEMM
    cudaFuncSetAttribute(int4_gemm_kernel,
                         cudaFuncAttributeMaxDynamicSharedMemorySize, SMEM_BYTES);
    dim3 grid(N_DIM / BN, M_DIM / BM);  // (86, 64)
    int4_gemm_kernel<<<grid, NTHREADS, SMEM_BYTES>>>(wp, scales, out);
}

// round 6
// speedup vs baseline: 1.2693x; 1.0404x over previous
#include <cuda_runtime.h>
#include <cuda_fp16.h>
#include <cstdint>

// Y[8192,11008] = X[8192,4096] (fp16-valued fp32) @ dequant(W4[11008,4096]).T
#define M_DIM 8192
#define N_DIM 11008
#define K_DIM 4096
#define BM 256
#define BN 128
#define BK 64
#define NTHREADS 256
#define STAGES 3

// shared: 3 A stages (32KB) + 2 B buffers (16KB) = 128KB
#define A_STAGE_BYTES (BM * BK * 2)
#define B_BUF_BYTES   (BN * BK * 2)
#define SMEM_BYTES (STAGES * A_STAGE_BYTES + 2 * B_BUF_BYTES)

// one-time fp16 copy of X (64 MB device scratch; fits L2)
__device__ __align__(16) __half g_xh[(size_t)M_DIM * K_DIM];

__device__ __forceinline__ void cp_async16(uint32_t dst, const void* src) {
    asm volatile("cp.async.cg.shared.global [%0], [%1], 16;\n" :: "r"(dst), "l"(src));
}
__device__ __forceinline__ void cp_commit() { asm volatile("cp.async.commit_group;\n"); }
__device__ __forceinline__ void cp_wait0()  { asm volatile("cp.async.wait_group 0;\n"); }
__device__ __forceinline__ void cp_wait1()  { asm volatile("cp.async.wait_group 1;\n"); }

__device__ __forceinline__ void ldsm_x4(uint32_t* r, uint32_t addr) {
    asm volatile("ldmatrix.sync.aligned.m8n8.x4.shared.b16 {%0,%1,%2,%3}, [%4];\n"
        : "=r"(r[0]), "=r"(r[1]), "=r"(r[2]), "=r"(r[3]) : "r"(addr));
}

__device__ __forceinline__ void mma_16816(float* c, const uint32_t* a, uint32_t b0, uint32_t b1) {
    asm volatile("mma.sync.aligned.m16n8k16.row.col.f32.f16.f16.f32 "
        "{%0,%1,%2,%3}, {%4,%5,%6,%7}, {%8,%9}, {%0,%1,%2,%3};\n"
        : "+f"(c[0]), "+f"(c[1]), "+f"(c[2]), "+f"(c[3])
        : "r"(a[0]), "r"(a[1]), "r"(a[2]), "r"(a[3]), "r"(b0), "r"(b1));
}

// fast int4-pair -> half2 dequant: exact same rounding as reference
// u = (1024+lo, 1024+hi) as half2; (u - 1032) exact; single fp16 mul rounding.
__device__ __forceinline__ uint32_t dq(uint32_t w, __half2 s2, __half2 h1032) {
    uint32_t u = ((w | (w << 12)) & 0x000F000Fu) | 0x64006400u;
    __half2 h = __hmul2(__hsub2(*(__half2*)&u, h1032), s2);
    return *(uint32_t*)&h;
}

// ---------------- kernel 1: X fp32 -> fp16 scratch ----------------
__global__ void __launch_bounds__(256, 4)
convert_x_kernel(const float* __restrict__ x)
{
    size_t i = ((size_t)blockIdx.x * 256 + threadIdx.x) * 8;
    float4 a0 = *(const float4*)(x + i);
    float4 a1 = *(const float4*)(x + i + 4);
    union { uint4 u; __half2 h[4]; } p;
    p.h[0] = __floats2half2_rn(a0.x, a0.y);
    p.h[1] = __floats2half2_rn(a0.z, a0.w);
    p.h[2] = __floats2half2_rn(a1.x, a1.y);
    p.h[3] = __floats2half2_rn(a1.z, a1.w);
    *(uint4*)(g_xh + i) = p.u;
}

// ---------------- kernel 2: fused dequant GEMM ----------------
__global__ void __launch_bounds__(NTHREADS, 1)
int4_gemm_kernel(const int*   __restrict__ wp,
                 const float* __restrict__ scales,
                 float*       __restrict__ out)
{
    extern __shared__ __half sm[];
    __half* Bs = sm + STAGES * BM * BK;

    const uint32_t smem_u = (uint32_t)__cvta_generic_to_shared(sm);
    const uint32_t As_u = smem_u;
    const uint32_t Bs_u = smem_u + STAGES * A_STAGE_BYTES;

    const int tid  = threadIdx.x;
    const int warp = tid >> 5;
    const int lane = tid & 31;
    const int m0 = blockIdx.x * BM;
    const int n0 = blockIdx.y * BN;

    // ---- staging maps ----
    // A: 256 rows x 8 chunks of 16B -> 8 chunks/thread (rows rbase+32i, i<8)
    // B: 128 rows x 8 chunks of 16B -> 4 chunks/thread (i<4)
    const int cv    = tid & 7;
    const int rbase = tid >> 3;            // 0..31
    const int cvs   = cv ^ (rbase & 7);    // XOR swizzle (row%8 invariant under +32)

    const __half* xg = g_xh + (size_t)(m0 + rbase) * K_DIM + cv * 8;
    const int*    wg = wp   + (size_t)(n0 + rbase) * (K_DIM / 2) + cv * 4;
    const float*  sg = scales + (size_t)(n0 + rbase) * (K_DIM / 128);
    const uint32_t st_off = ((uint32_t)(rbase * BK + cvs * 8)) * 2;  // bytes, +i*4096

    // ---- warp tiling: 8 warps = 4(m) x 2(n); warp tile 64x64 ----
    const int wm  = (warp >> 1) * 64;
    const int wn  = (warp & 1) * 64;
    const int lrA = lane & 15;
    const int lkA = lane >> 4;
    const int lrB = (lane & 7) + ((lane >> 4) << 3);
    const int lkB = (lane >> 3) & 1;

    const __half2 h1032 = __half2half2(__ushort_as_half((unsigned short)0x6408));

    float acc[4][8][4];
    #pragma unroll
    for (int i = 0; i < 4; i++)
        #pragma unroll
        for (int j = 0; j < 8; j++)
            #pragma unroll
            for (int q = 0; q < 4; q++) acc[i][j][q] = 0.f;

    const int KT = K_DIM / BK;  // 64

    // ================= prologue =================
    #pragma unroll
    for (int s = 0; s < 2; s++) {
        #pragma unroll
        for (int i = 0; i < 8; i++)
            cp_async16(As_u + s * A_STAGE_BYTES + st_off + i * 4096,
                       xg + (size_t)(32 * i) * K_DIM + s * BK);
        cp_commit();
    }
    #pragma unroll
    for (int i = 0; i < 4; i++) {
        uint4 wv = *(const uint4*)(wg + (size_t)(32 * i) * (K_DIM / 2));
        __half2 s2 = __half2half2(__float2half_rn(sg[(size_t)(32 * i) * (K_DIM / 128)]));
        uint4 pb;
        pb.x = dq(wv.x, s2, h1032);
        pb.y = dq(wv.y, s2, h1032);
        pb.z = dq(wv.z, s2, h1032);
        pb.w = dq(wv.w, s2, h1032);
        *(uint4*)(Bs + st_off / 2 + i * 2048) = pb;
    }
    cp_wait1();
    __syncthreads();

    // ================= main loop =================
    for (int kt = 0; kt < KT; kt++) {
        const int abuf = kt % STAGES;
        const int bbuf = kt & 1;

        // issue A(kt+2)
        if (kt + 2 < KT) {
            const int s = (kt + 2) % STAGES;
            #pragma unroll
            for (int i = 0; i < 8; i++)
                cp_async16(As_u + s * A_STAGE_BYTES + st_off + i * 4096,
                           xg + (size_t)(32 * i) * K_DIM + (kt + 2) * BK);
            cp_commit();
        }

        // prefetch B(kt+1) packed + scale into regs
        uint4 wv[4];
        __half2 s2[4];
        if (kt + 1 < KT) {
            const int g = (kt + 1) >> 1;
            #pragma unroll
            for (int i = 0; i < 4; i++) {
                wv[i] = *(const uint4*)(wg + (size_t)(32 * i) * (K_DIM / 2) + (kt + 1) * (BK / 2));
                s2[i] = __half2half2(__float2half_rn(sg[(size_t)(32 * i) * (K_DIM / 128) + g]));
            }
        }

        // ---- compute ktile kt ----
        const uint32_t ab = As_u + abuf * A_STAGE_BYTES;
        const uint32_t bb = Bs_u + bbuf * B_BUF_BYTES;
        #pragma unroll
        for (int ks = 0; ks < 4; ks++) {
            uint32_t a[4][4], b[4][4];
            #pragma unroll
            for (int i = 0; i < 4; i++) {
                int r  = wm + i * 16 + lrA;
                int ch = 2 * ks + lkA;
                ldsm_x4(a[i], ab + (uint32_t)(r * BK + ((ch ^ (r & 7)) << 3)) * 2);
            }
            #pragma unroll
            for (int p = 0; p < 4; p++) {
                int r  = wn + p * 16 + lrB;
                int ch = 2 * ks + lkB;
                ldsm_x4(b[p], bb + (uint32_t)(r * BK + ((ch ^ (r & 7)) << 3)) * 2);
            }
            #pragma unroll
            for (int i = 0; i < 4; i++)
                #pragma unroll
                for (int j = 0; j < 8; j++)
                    mma_16816(acc[i][j], a[i], b[j >> 1][(j & 1) * 2], b[j >> 1][(j & 1) * 2 + 1]);
        }

        // dequant B(kt+1) -> other buffer, close stage
        if (kt + 1 < KT) {
            #pragma unroll
            for (int i = 0; i < 4; i++) {
                uint4 pb;
                pb.x = dq(wv[i].x, s2[i], h1032);
                pb.y = dq(wv[i].y, s2[i], h1032);
                pb.z = dq(wv[i].z, s2[i], h1032);
                pb.w = dq(wv[i].w, s2[i], h1032);
                *(uint4*)(Bs + (bbuf ^ 1) * (BN * BK) + st_off / 2 + i * 2048) = pb;
            }
            if (kt + 2 < KT) cp_wait1(); else cp_wait0();
            __syncthreads();
        }
    }

    // ================= epilogue (fp32 out, rounded through fp16 like ref) =================
    const int g  = lane >> 2;
    const int tc = lane & 3;
    #pragma unroll
    for (int i = 0; i < 4; i++) {
        #pragma unroll
        for (int j = 0; j < 8; j++) {
            int row = m0 + wm + i * 16 + g;
            int col = n0 + wn + j * 8 + tc * 2;
            float2 v0, v1;
            v0.x = __half2float(__float2half_rn(acc[i][j][0]));
            v0.y = __half2float(__float2half_rn(acc[i][j][1]));
            v1.x = __half2float(__float2half_rn(acc[i][j][2]));
            v1.y = __half2float(__float2half_rn(acc[i][j][3]));
            *(float2*)(out + (size_t)row * N_DIM + col)       = v0;
            *(float2*)(out + (size_t)(row + 8) * N_DIM + col) = v1;
        }
    }
}

extern "C" void kernel_launch(void* const* d_in, const int* in_sizes, int n_in,
                              void* d_out, int out_size)
{
    const float* x      = (const float*)d_in[0];
    const int*   wp     = (const int*)d_in[1];
    const float* scales = (const float*)d_in[2];
    for (int i = 0; i < n_in; i++) {
        if (in_sizes[i] == 33554432)      x      = (const float*)d_in[i];
        else if (in_sizes[i] == 22544384) wp     = (const int*)d_in[i];
        else if (in_sizes[i] == 352256)   scales = (const float*)d_in[i];
    }
    float* out = (float*)d_out;

    convert_x_kernel<<<(size_t)M_DIM * K_DIM / (256 * 8), 256>>>(x);

    cudaFuncSetAttribute(int4_gemm_kernel,
                         cudaFuncAttributeMaxDynamicSharedMemorySize, SMEM_BYTES);
    dim3 grid(M_DIM / BM, N_DIM / BN);  // (32, 86): m fastest -> X stays L2-hot
    int4_gemm_kernel<<<grid, NTHREADS, SMEM_BYTES>>>(wp, scales, out);
}